// round 8
// baseline (speedup 1.0000x reference)
#include <cuda_runtime.h>
#include <cuda_fp16.h>

#define N_NODES 100000
#define N_EDGES 1000000
#define FB_GRID 592
#define FB_STRIDE (FB_GRID * 256)          // 151552
#define N4 (N_NODES * 4)                   // 400000 float4 slots

__device__ __half g_t[N_NODES * 64];    // [n][o][c] fp16: t[n,o,c] = sum_i v[n,i]*W[i*16+o][c]
__device__ __half g_tb[N_NODES * 16];   // [n][o]    fp16: tb[n,o] = sum_i v[n,i]*b[i*16+o]
__device__ float  g_r[N_NODES * 16];    // [n][o]    fp32: v@root + bias (node-local term)
__device__ float  g_sum[N_NODES * 16];  // scatter accumulator
__device__ float  g_cnt[N_NODES];       // degree accumulator
__device__ float  g_s1[16];             // batch sum per feature
__device__ float  g_s2[16];             // batch sum-of-squares per feature
__device__ int    g_ctr;                // grid-barrier counter

// ---------------------------------------------------------------------------
// K1 (launch 1): per-node precompute of t/tb/r, PLUS zeroing of all
// accumulators (fused former k_zero + k_statzero).
// 6250 blocks x 256 threads; block b handles nodes [16b, 16b+16).
// ---------------------------------------------------------------------------
__global__ void __launch_bounds__(256) k_node_pre(
    const float* __restrict__ v,
    const float* __restrict__ enet_w,   // [256][4]
    const float* __restrict__ enet_b,   // [256]
    const float* __restrict__ root,     // [16][16] (i,o)
    const float* __restrict__ bias)     // [16]
{
    __shared__ float sw[1024];
    __shared__ float sb[256];
    __shared__ float sroot[256];
    __shared__ float sv[256];
    int t = threadIdx.x;
    unsigned gid = blockIdx.x * 256u + t;

    // --- fused zeroing (1.6M threads cover everything in one shot) ---
    if (gid < N4) reinterpret_cast<float4*>(g_sum)[gid] = make_float4(0.f, 0.f, 0.f, 0.f);
    if (gid < N_NODES) g_cnt[gid] = 0.0f;
    if (gid < 16) { g_s1[gid] = 0.0f; g_s2[gid] = 0.0f; }
    if (gid == 16) g_ctr = 0;

    for (int i = t; i < 1024; i += 256) sw[i] = enet_w[i];
    sb[t] = enet_b[t];
    sroot[t] = root[t];
    int nbase = blockIdx.x * 16;
    sv[t] = v[nbase * 16 + t];
    __syncthreads();

    int nl = t >> 4;
    int o = t & 15;
    int n = nbase + nl;          // grid sized exactly: n < N_NODES always

    float a0 = 0.f, a1 = 0.f, a2 = 0.f, a3 = 0.f, ab = 0.f, ar = bias[o];
    const float* vrow = sv + nl * 16;
#pragma unroll
    for (int i = 0; i < 16; i++) {
        float vi = vrow[i];
        int j = i * 16 + o;
        const float* w4 = sw + j * 4;
        a0 = fmaf(vi, w4[0], a0);
        a1 = fmaf(vi, w4[1], a1);
        a2 = fmaf(vi, w4[2], a2);
        a3 = fmaf(vi, w4[3], a3);
        ab = fmaf(vi, sb[j], ab);
        ar = fmaf(vi, sroot[j], ar);
    }
    __half2 h01 = __floats2half2_rn(a0, a1);
    __half2 h23 = __floats2half2_rn(a2, a3);
    uint2 pk;
    pk.x = *reinterpret_cast<unsigned*>(&h01);
    pk.y = *reinterpret_cast<unsigned*>(&h23);
    *reinterpret_cast<uint2*>(g_t + (unsigned)n * 64u + (unsigned)o * 4u) = pk;
    g_tb[(unsigned)n * 16u + o] = __float2half_rn(ab);
    g_r[(unsigned)n * 16u + o] = ar;
}

// ---------------------------------------------------------------------------
// K2 (launch 2): per-edge message + vector RED scatter.
// Quad of 4 threads per edge; thread j covers outputs 4j..4j+3.
// ---------------------------------------------------------------------------
__global__ void __launch_bounds__(256) k_edge(
    const float* __restrict__ efeat,
    const int* __restrict__ ei)   // [2][E] row0=src, row1=dst
{
    unsigned gid = blockIdx.x * 256u + threadIdx.x;
    unsigned eid = gid >> 2;
    unsigned j = gid & 3u;
    if (eid >= N_EDGES) return;

    int src = ei[eid];
    int dst = ei[N_EDGES + eid];

    float4 ev = __ldg(reinterpret_cast<const float4*>(efeat) + eid);

    const uint4* tp = reinterpret_cast<const uint4*>(g_t + (unsigned)src * 64u + j * 16u);
    uint4 ta = __ldg(tp);
    uint4 tb = __ldg(tp + 1);
    uint2 tbr = __ldg(reinterpret_cast<const uint2*>(g_tb + (unsigned)src * 16u + j * 4u));

#define H2F(u) __half22float2(*reinterpret_cast<__half2*>(&(u)))
    float2 b01 = H2F(tbr.x), b23 = H2F(tbr.y);
    float2 c0 = H2F(ta.x), c1 = H2F(ta.y), c2 = H2F(ta.z), c3 = H2F(ta.w);
    float2 c4 = H2F(tb.x), c5 = H2F(tb.y), c6 = H2F(tb.z), c7 = H2F(tb.w);
#undef H2F
    float m0 = fmaf(ev.x, c0.x, fmaf(ev.y, c0.y, fmaf(ev.z, c1.x, fmaf(ev.w, c1.y, b01.x))));
    float m1 = fmaf(ev.x, c2.x, fmaf(ev.y, c2.y, fmaf(ev.z, c3.x, fmaf(ev.w, c3.y, b01.y))));
    float m2 = fmaf(ev.x, c4.x, fmaf(ev.y, c4.y, fmaf(ev.z, c5.x, fmaf(ev.w, c5.y, b23.x))));
    float m3 = fmaf(ev.x, c6.x, fmaf(ev.y, c6.y, fmaf(ev.z, c7.x, fmaf(ev.w, c7.y, b23.y))));

    float* outp = g_sum + (unsigned)dst * 16u + j * 4u;
    asm volatile("red.global.add.v4.f32 [%0], {%1, %2, %3, %4};"
                 :: "l"(outp), "f"(m0), "f"(m1), "f"(m2), "f"(m3) : "memory");
    if (j == 0) {
        float* cp = g_cnt + dst;
        asm volatile("red.global.add.f32 [%0], %1;" :: "l"(cp), "f"(1.0f) : "memory");
    }
}

// ---------------------------------------------------------------------------
// K3 (launch 3): fused finalize + BatchNorm + LeakyReLU with a software
// grid barrier. 592 blocks <= full-residency capacity (148 SMs x 8 CTAs),
// so the spin cannot deadlock. Values held in registers across the barrier.
// ---------------------------------------------------------------------------
__global__ void __launch_bounds__(256) k_finalbn(
    float* __restrict__ out,
    const float* __restrict__ gamma,
    const float* __restrict__ beta)
{
    int t = threadIdx.x;
    int idx = blockIdx.x * 256 + t;
    const float4* s4 = reinterpret_cast<const float4*>(g_sum);
    const float4* r4 = reinterpret_cast<const float4*>(g_r);
    float4* o4 = reinterpret_cast<float4*>(out);

    // ---- phase 1: compute pre-BN values, keep in registers, gather stats ----
    float4 vals[3];
    float s1x = 0.f, s1y = 0.f, s1z = 0.f, s1w = 0.f;
    float s2x = 0.f, s2y = 0.f, s2z = 0.f, s2w = 0.f;
#pragma unroll
    for (int k = 0; k < 3; k++) {
        int i = idx + k * FB_STRIDE;
        if (i < N4) {
            int n = i >> 2;
            float inv = 1.0f / fmaxf(g_cnt[n], 1.0f);
            float4 s = s4[i];
            float4 r = r4[i];
            float4 val;
            val.x = fmaf(s.x, inv, r.x);
            val.y = fmaf(s.y, inv, r.y);
            val.z = fmaf(s.z, inv, r.z);
            val.w = fmaf(s.w, inv, r.w);
            vals[k] = val;
            s1x += val.x; s1y += val.y; s1z += val.z; s1w += val.w;
            s2x = fmaf(val.x, val.x, s2x);
            s2y = fmaf(val.y, val.y, s2y);
            s2z = fmaf(val.z, val.z, s2z);
            s2w = fmaf(val.w, val.w, s2w);
        }
    }

    // ---- block-level stat reduction (same o for lanes with equal lane&3) ----
#pragma unroll
    for (int m = 4; m <= 16; m <<= 1) {
        s1x += __shfl_xor_sync(0xffffffffu, s1x, m);
        s1y += __shfl_xor_sync(0xffffffffu, s1y, m);
        s1z += __shfl_xor_sync(0xffffffffu, s1z, m);
        s1w += __shfl_xor_sync(0xffffffffu, s1w, m);
        s2x += __shfl_xor_sync(0xffffffffu, s2x, m);
        s2y += __shfl_xor_sync(0xffffffffu, s2y, m);
        s2z += __shfl_xor_sync(0xffffffffu, s2z, m);
        s2w += __shfl_xor_sync(0xffffffffu, s2w, m);
    }
    __shared__ float sm1[8][4][4];
    __shared__ float sm2[8][4][4];
    int warp = t >> 5;
    int lane = t & 31;
    if (lane < 4) {
        sm1[warp][lane][0] = s1x; sm1[warp][lane][1] = s1y;
        sm1[warp][lane][2] = s1z; sm1[warp][lane][3] = s1w;
        sm2[warp][lane][0] = s2x; sm2[warp][lane][1] = s2y;
        sm2[warp][lane][2] = s2z; sm2[warp][lane][3] = s2w;
    }
    __syncthreads();
    if (t < 16) {
        float a1 = 0.f, a2 = 0.f;
#pragma unroll
        for (int w = 0; w < 8; w++) {
            a1 += sm1[w][t >> 2][t & 3];
            a2 += sm2[w][t >> 2][t & 3];
        }
        atomicAdd(&g_s1[t], a1);
        atomicAdd(&g_s2[t], a2);
    }

    // ---- grid barrier (threadfence-reduction pattern) ----
    __threadfence();
    __syncthreads();
    if (t == 0) {
        atomicAdd(&g_ctr, 1);
        while (atomicAdd(&g_ctr, 0) < FB_GRID) { }
    }
    __syncthreads();

    // ---- phase 2: BN + LeakyReLU on register-held values ----
    int ob = (idx & 3) * 4;               // FB_STRIDE % 4 == 0 -> invariant
    const float invN = 1.0f / (float)N_NODES;
    float scale[4], shift[4];
#pragma unroll
    for (int k = 0; k < 4; k++) {
        int o = ob + k;
        float mu = __ldcg(&g_s1[o]) * invN;
        float var = __ldcg(&g_s2[o]) * invN - mu * mu;
        float sc = gamma[o] * rsqrtf(var + 1e-5f);
        scale[k] = sc;
        shift[k] = beta[o] - sc * mu;
    }
#pragma unroll
    for (int k = 0; k < 3; k++) {
        int i = idx + k * FB_STRIDE;
        if (i < N4) {
            float4 val = vals[k];
            float x0 = fmaf(val.x, scale[0], shift[0]);
            float x1 = fmaf(val.y, scale[1], shift[1]);
            float x2 = fmaf(val.z, scale[2], shift[2]);
            float x3 = fmaf(val.w, scale[3], shift[3]);
            float4 res;
            res.x = (x0 >= 0.0f) ? x0 : 0.01f * x0;
            res.y = (x1 >= 0.0f) ? x1 : 0.01f * x1;
            res.z = (x2 >= 0.0f) ? x2 : 0.01f * x2;
            res.w = (x3 >= 0.0f) ? x3 : 0.01f * x3;
            o4[i] = res;
        }
    }
}

// ---------------------------------------------------------------------------
extern "C" void kernel_launch(void* const* d_in, const int* in_sizes, int n_in,
                              void* d_out, int out_size) {
    const float* v      = (const float*)d_in[0];
    const float* e      = (const float*)d_in[1];
    const int*   ei     = (const int*)  d_in[2];
    const float* enet_w = (const float*)d_in[3];
    const float* enet_b = (const float*)d_in[4];
    const float* root   = (const float*)d_in[5];
    const float* bias   = (const float*)d_in[6];
    const float* gamma  = (const float*)d_in[7];
    const float* beta   = (const float*)d_in[8];
    float* out = (float*)d_out;

    k_node_pre<<<N_NODES / 16, 256>>>(v, enet_w, enet_b, root, bias);  // launch 1
    k_edge    <<<(N_EDGES * 4) / 256, 256>>>(e, ei);                   // launch 2
    k_finalbn <<<FB_GRID, 256>>>(out, gamma, beta);                    // launch 3
}

// round 9
// speedup vs baseline: 1.0062x; 1.0062x over previous
#include <cuda_runtime.h>
#include <cuda_fp16.h>

#define N_NODES 100000
#define N_EDGES 1000000
#define FB_GRID 592
#define FB_STRIDE (FB_GRID * 256)          // 151552
#define N4 (N_NODES * 4)                   // 400000 float4 slots

__device__ __half g_t[N_NODES * 64];    // [n][o][c] fp16: t[n,o,c] = sum_i v[n,i]*W[i*16+o][c]
__device__ __half g_tb[N_NODES * 16];   // [n][o]    fp16: tb[n,o] = sum_i v[n,i]*b[i*16+o]
__device__ float  g_r[N_NODES * 16];    // [n][o]    fp32: v@root + bias (node-local term)
__device__ float  g_sum[N_NODES * 16];  // scatter accumulator
__device__ float  g_cnt[N_NODES];       // degree accumulator
__device__ float  g_s1[16];             // batch sum per feature
__device__ float  g_s2[16];             // batch sum-of-squares per feature
__device__ int    g_ctr;                // grid-barrier counter

// ---------------------------------------------------------------------------
// K1 (launch 1): per-node precompute of t/tb/r, PLUS zeroing of all
// accumulators (fused former k_zero + k_statzero).
// 6250 blocks x 256 threads; block b handles nodes [16b, 16b+16).
// ---------------------------------------------------------------------------
__global__ void __launch_bounds__(256) k_node_pre(
    const float* __restrict__ v,
    const float* __restrict__ enet_w,   // [256][4]
    const float* __restrict__ enet_b,   // [256]
    const float* __restrict__ root,     // [16][16] (i,o)
    const float* __restrict__ bias)     // [16]
{
    __shared__ float sw[1024];
    __shared__ float sb[256];
    __shared__ float sroot[256];
    __shared__ float sv[256];
    int t = threadIdx.x;
    unsigned gid = blockIdx.x * 256u + t;

    // --- fused zeroing (1.6M threads cover everything in one shot) ---
    if (gid < N4) reinterpret_cast<float4*>(g_sum)[gid] = make_float4(0.f, 0.f, 0.f, 0.f);
    if (gid < N_NODES) g_cnt[gid] = 0.0f;
    if (gid < 16) { g_s1[gid] = 0.0f; g_s2[gid] = 0.0f; }
    if (gid == 16) g_ctr = 0;

    for (int i = t; i < 1024; i += 256) sw[i] = enet_w[i];
    sb[t] = enet_b[t];
    sroot[t] = root[t];
    int nbase = blockIdx.x * 16;
    sv[t] = v[nbase * 16 + t];
    __syncthreads();

    int nl = t >> 4;
    int o = t & 15;
    int n = nbase + nl;          // grid sized exactly: n < N_NODES always

    float a0 = 0.f, a1 = 0.f, a2 = 0.f, a3 = 0.f, ab = 0.f, ar = bias[o];
    const float* vrow = sv + nl * 16;
#pragma unroll
    for (int i = 0; i < 16; i++) {
        float vi = vrow[i];
        int j = i * 16 + o;
        const float* w4 = sw + j * 4;
        a0 = fmaf(vi, w4[0], a0);
        a1 = fmaf(vi, w4[1], a1);
        a2 = fmaf(vi, w4[2], a2);
        a3 = fmaf(vi, w4[3], a3);
        ab = fmaf(vi, sb[j], ab);
        ar = fmaf(vi, sroot[j], ar);
    }
    __half2 h01 = __floats2half2_rn(a0, a1);
    __half2 h23 = __floats2half2_rn(a2, a3);
    uint2 pk;
    pk.x = *reinterpret_cast<unsigned*>(&h01);
    pk.y = *reinterpret_cast<unsigned*>(&h23);
    *reinterpret_cast<uint2*>(g_t + (unsigned)n * 64u + (unsigned)o * 4u) = pk;
    g_tb[(unsigned)n * 16u + o] = __float2half_rn(ab);
    g_r[(unsigned)n * 16u + o] = ar;
}

// ---------------------------------------------------------------------------
// K2 (launch 2): per-edge message + vector RED scatter.
// Quad of 4 threads per edge; thread j covers outputs 4j..4j+3.
// ---------------------------------------------------------------------------
__global__ void __launch_bounds__(256) k_edge(
    const float* __restrict__ efeat,
    const int* __restrict__ ei)   // [2][E] row0=src, row1=dst
{
    unsigned gid = blockIdx.x * 256u + threadIdx.x;
    unsigned eid = gid >> 2;
    unsigned j = gid & 3u;
    if (eid >= N_EDGES) return;

    int src = ei[eid];
    int dst = ei[N_EDGES + eid];

    float4 ev = __ldg(reinterpret_cast<const float4*>(efeat) + eid);

    const uint4* tp = reinterpret_cast<const uint4*>(g_t + (unsigned)src * 64u + j * 16u);
    uint4 ta = __ldg(tp);
    uint4 tb = __ldg(tp + 1);
    uint2 tbr = __ldg(reinterpret_cast<const uint2*>(g_tb + (unsigned)src * 16u + j * 4u));

#define H2F(u) __half22float2(*reinterpret_cast<__half2*>(&(u)))
    float2 b01 = H2F(tbr.x), b23 = H2F(tbr.y);
    float2 c0 = H2F(ta.x), c1 = H2F(ta.y), c2 = H2F(ta.z), c3 = H2F(ta.w);
    float2 c4 = H2F(tb.x), c5 = H2F(tb.y), c6 = H2F(tb.z), c7 = H2F(tb.w);
#undef H2F
    float m0 = fmaf(ev.x, c0.x, fmaf(ev.y, c0.y, fmaf(ev.z, c1.x, fmaf(ev.w, c1.y, b01.x))));
    float m1 = fmaf(ev.x, c2.x, fmaf(ev.y, c2.y, fmaf(ev.z, c3.x, fmaf(ev.w, c3.y, b01.y))));
    float m2 = fmaf(ev.x, c4.x, fmaf(ev.y, c4.y, fmaf(ev.z, c5.x, fmaf(ev.w, c5.y, b23.x))));
    float m3 = fmaf(ev.x, c6.x, fmaf(ev.y, c6.y, fmaf(ev.z, c7.x, fmaf(ev.w, c7.y, b23.y))));

    float* outp = g_sum + (unsigned)dst * 16u + j * 4u;
    asm volatile("red.global.add.v4.f32 [%0], {%1, %2, %3, %4};"
                 :: "l"(outp), "f"(m0), "f"(m1), "f"(m2), "f"(m3) : "memory");
    if (j == 0) {
        float* cp = g_cnt + dst;
        asm volatile("red.global.add.f32 [%0], %1;" :: "l"(cp), "f"(1.0f) : "memory");
    }
}

// ---------------------------------------------------------------------------
// K3 (launch 3): fused finalize + BatchNorm + LeakyReLU with a software
// grid barrier. 592 blocks <= full-residency capacity (148 SMs x 8 CTAs),
// so the spin cannot deadlock. Values held in registers across the barrier.
// ---------------------------------------------------------------------------
__global__ void __launch_bounds__(256) k_finalbn(
    float* __restrict__ out,
    const float* __restrict__ gamma,
    const float* __restrict__ beta)
{
    int t = threadIdx.x;
    int idx = blockIdx.x * 256 + t;
    const float4* s4 = reinterpret_cast<const float4*>(g_sum);
    const float4* r4 = reinterpret_cast<const float4*>(g_r);
    float4* o4 = reinterpret_cast<float4*>(out);

    // ---- phase 1: compute pre-BN values, keep in registers, gather stats ----
    float4 vals[3];
    float s1x = 0.f, s1y = 0.f, s1z = 0.f, s1w = 0.f;
    float s2x = 0.f, s2y = 0.f, s2z = 0.f, s2w = 0.f;
#pragma unroll
    for (int k = 0; k < 3; k++) {
        int i = idx + k * FB_STRIDE;
        if (i < N4) {
            int n = i >> 2;
            float inv = 1.0f / fmaxf(g_cnt[n], 1.0f);
            float4 s = s4[i];
            float4 r = r4[i];
            float4 val;
            val.x = fmaf(s.x, inv, r.x);
            val.y = fmaf(s.y, inv, r.y);
            val.z = fmaf(s.z, inv, r.z);
            val.w = fmaf(s.w, inv, r.w);
            vals[k] = val;
            s1x += val.x; s1y += val.y; s1z += val.z; s1w += val.w;
            s2x = fmaf(val.x, val.x, s2x);
            s2y = fmaf(val.y, val.y, s2y);
            s2z = fmaf(val.z, val.z, s2z);
            s2w = fmaf(val.w, val.w, s2w);
        }
    }

    // ---- block-level stat reduction (same o for lanes with equal lane&3) ----
#pragma unroll
    for (int m = 4; m <= 16; m <<= 1) {
        s1x += __shfl_xor_sync(0xffffffffu, s1x, m);
        s1y += __shfl_xor_sync(0xffffffffu, s1y, m);
        s1z += __shfl_xor_sync(0xffffffffu, s1z, m);
        s1w += __shfl_xor_sync(0xffffffffu, s1w, m);
        s2x += __shfl_xor_sync(0xffffffffu, s2x, m);
        s2y += __shfl_xor_sync(0xffffffffu, s2y, m);
        s2z += __shfl_xor_sync(0xffffffffu, s2z, m);
        s2w += __shfl_xor_sync(0xffffffffu, s2w, m);
    }
    __shared__ float sm1[8][4][4];
    __shared__ float sm2[8][4][4];
    int warp = t >> 5;
    int lane = t & 31;
    if (lane < 4) {
        sm1[warp][lane][0] = s1x; sm1[warp][lane][1] = s1y;
        sm1[warp][lane][2] = s1z; sm1[warp][lane][3] = s1w;
        sm2[warp][lane][0] = s2x; sm2[warp][lane][1] = s2y;
        sm2[warp][lane][2] = s2z; sm2[warp][lane][3] = s2w;
    }
    __syncthreads();
    if (t < 16) {
        float a1 = 0.f, a2 = 0.f;
#pragma unroll
        for (int w = 0; w < 8; w++) {
            a1 += sm1[w][t >> 2][t & 3];
            a2 += sm2[w][t >> 2][t & 3];
        }
        atomicAdd(&g_s1[t], a1);
        atomicAdd(&g_s2[t], a2);
    }

    // ---- grid barrier (threadfence-reduction pattern) ----
    __threadfence();
    __syncthreads();
    if (t == 0) {
        atomicAdd(&g_ctr, 1);
        while (atomicAdd(&g_ctr, 0) < FB_GRID) { }
    }
    __syncthreads();

    // ---- phase 2: BN + LeakyReLU on register-held values ----
    int ob = (idx & 3) * 4;               // FB_STRIDE % 4 == 0 -> invariant
    const float invN = 1.0f / (float)N_NODES;
    float scale[4], shift[4];
#pragma unroll
    for (int k = 0; k < 4; k++) {
        int o = ob + k;
        float mu = __ldcg(&g_s1[o]) * invN;
        float var = __ldcg(&g_s2[o]) * invN - mu * mu;
        float sc = gamma[o] * rsqrtf(var + 1e-5f);
        scale[k] = sc;
        shift[k] = beta[o] - sc * mu;
    }
#pragma unroll
    for (int k = 0; k < 3; k++) {
        int i = idx + k * FB_STRIDE;
        if (i < N4) {
            float4 val = vals[k];
            float x0 = fmaf(val.x, scale[0], shift[0]);
            float x1 = fmaf(val.y, scale[1], shift[1]);
            float x2 = fmaf(val.z, scale[2], shift[2]);
            float x3 = fmaf(val.w, scale[3], shift[3]);
            float4 res;
            res.x = (x0 >= 0.0f) ? x0 : 0.01f * x0;
            res.y = (x1 >= 0.0f) ? x1 : 0.01f * x1;
            res.z = (x2 >= 0.0f) ? x2 : 0.01f * x2;
            res.w = (x3 >= 0.0f) ? x3 : 0.01f * x3;
            o4[i] = res;
        }
    }
}

// ---------------------------------------------------------------------------
extern "C" void kernel_launch(void* const* d_in, const int* in_sizes, int n_in,
                              void* d_out, int out_size) {
    const float* v      = (const float*)d_in[0];
    const float* e      = (const float*)d_in[1];
    const int*   ei     = (const int*)  d_in[2];
    const float* enet_w = (const float*)d_in[3];
    const float* enet_b = (const float*)d_in[4];
    const float* root   = (const float*)d_in[5];
    const float* bias   = (const float*)d_in[6];
    const float* gamma  = (const float*)d_in[7];
    const float* beta   = (const float*)d_in[8];
    float* out = (float*)d_out;

    k_node_pre<<<N_NODES / 16, 256>>>(v, enet_w, enet_b, root, bias);  // launch 1
    k_edge    <<<(N_EDGES * 4) / 256, 256>>>(e, ei);                   // launch 2
    k_finalbn <<<FB_GRID, 256>>>(out, gamma, beta);                    // launch 3
}

// round 10
// speedup vs baseline: 1.0303x; 1.0239x over previous
#include <cuda_runtime.h>
#include <cuda_fp16.h>

#define N_NODES 100000
#define N_EDGES 1000000
#define FB_GRID 592
#define FB_STRIDE (FB_GRID * 256)          // 151552
#define N4 (N_NODES * 4)                   // 400000 float4 slots

typedef unsigned long long ull;

#define PACK2(d, lo, hi)  asm("mov.b64 %0, {%1, %2};" : "=l"(d) : "f"(lo), "f"(hi))
#define UNPACK2(lo, hi, s) asm("mov.b64 {%0, %1}, %2;" : "=f"(lo), "=f"(hi) : "l"(s))
#define FMA2(d, a, b, c)  asm("fma.rn.f32x2 %0, %1, %2, %3;" : "=l"(d) : "l"(a), "l"(b), "l"(c))

__device__ __half g_t[N_NODES * 64];    // [n][o][c] fp16: t[n,o,c] = sum_i v[n,i]*W[i*16+o][c]
__device__ __half g_tb[N_NODES * 16];   // [n][o]    fp16: tb[n,o] = sum_i v[n,i]*b[i*16+o]
__device__ float  g_r[N_NODES * 16];    // [n][o]    fp32: v@root + bias (node-local term)
__device__ float  g_sum[N_NODES * 16];  // scatter accumulator
__device__ float  g_cnt[N_NODES];       // degree accumulator
__device__ float  g_s1[16];             // batch sum per feature
__device__ float  g_s2[16];             // batch sum-of-squares per feature
__device__ int    g_ctr;                // grid-barrier counter

// ---------------------------------------------------------------------------
// K1 (launch 1): per-node precompute of t/tb/r + fused zeroing.
// Inner loop: 1 LDS.128 (w float4) + 1 LDS.64 (b,root float2) + 3 FFMA2.
// ---------------------------------------------------------------------------
__global__ void __launch_bounds__(256) k_node_pre(
    const float* __restrict__ v,
    const float* __restrict__ enet_w,   // [256][4]
    const float* __restrict__ enet_b,   // [256]
    const float* __restrict__ root,     // [16][16] (i,o)
    const float* __restrict__ bias)     // [16]
{
    __shared__ float4 sw4[256];     // [j] = W row j (4 floats)
    __shared__ float2 sbr[256];     // [j] = (enet_b[j], root[j])
    __shared__ float  sv[256];
    int t = threadIdx.x;
    unsigned gid = blockIdx.x * 256u + t;

    // --- fused zeroing ---
    if (gid < N4) reinterpret_cast<float4*>(g_sum)[gid] = make_float4(0.f, 0.f, 0.f, 0.f);
    if (gid < N_NODES) g_cnt[gid] = 0.0f;
    if (gid < 16) { g_s1[gid] = 0.0f; g_s2[gid] = 0.0f; }
    if (gid == 16) g_ctr = 0;

    sw4[t] = reinterpret_cast<const float4*>(enet_w)[t];
    sbr[t] = make_float2(enet_b[t], root[t]);
    int nbase = blockIdx.x * 16;
    sv[t] = v[nbase * 16 + t];
    __syncthreads();

    int nl = t >> 4;
    int o = t & 15;
    int n = nbase + nl;

    // hoist v row into registers, prepacked as f32x2 broadcast pairs
    ull vr2[16];
#pragma unroll
    for (int q = 0; q < 4; q++) {
        float4 x = *reinterpret_cast<const float4*>(sv + nl * 16 + q * 4);
        PACK2(vr2[q * 4 + 0], x.x, x.x);
        PACK2(vr2[q * 4 + 1], x.y, x.y);
        PACK2(vr2[q * 4 + 2], x.z, x.z);
        PACK2(vr2[q * 4 + 3], x.w, x.w);
    }

    ull a01, a23, abr;
    PACK2(a01, 0.0f, 0.0f);
    PACK2(a23, 0.0f, 0.0f);
    {
        float b = bias[o];
        PACK2(abr, 0.0f, b);      // (tb_acc, r_acc) ; r starts at bias
    }

#pragma unroll
    for (int i = 0; i < 16; i++) {
        int j = i * 16 + o;
        float4 w = sw4[j];
        float2 br = sbr[j];
        ull w01, w23, brp;
        PACK2(w01, w.x, w.y);
        PACK2(w23, w.z, w.w);
        PACK2(brp, br.x, br.y);
        FMA2(a01, vr2[i], w01, a01);
        FMA2(a23, vr2[i], w23, a23);
        FMA2(abr, vr2[i], brp, abr);
    }

    float a0, a1, a2, a3, ab, ar;
    UNPACK2(a0, a1, a01);
    UNPACK2(a2, a3, a23);
    UNPACK2(ab, ar, abr);

    __half2 h01 = __floats2half2_rn(a0, a1);
    __half2 h23 = __floats2half2_rn(a2, a3);
    uint2 pk;
    pk.x = *reinterpret_cast<unsigned*>(&h01);
    pk.y = *reinterpret_cast<unsigned*>(&h23);
    *reinterpret_cast<uint2*>(g_t + (unsigned)n * 64u + (unsigned)o * 4u) = pk;
    g_tb[(unsigned)n * 16u + o] = __float2half_rn(ab);
    g_r[(unsigned)n * 16u + o] = ar;
}

// ---------------------------------------------------------------------------
// K2 (launch 2): per-edge message + vector RED scatter. (unchanged)
// ---------------------------------------------------------------------------
__global__ void __launch_bounds__(256) k_edge(
    const float* __restrict__ efeat,
    const int* __restrict__ ei)   // [2][E] row0=src, row1=dst
{
    unsigned gid = blockIdx.x * 256u + threadIdx.x;
    unsigned eid = gid >> 2;
    unsigned j = gid & 3u;
    if (eid >= N_EDGES) return;

    int src = ei[eid];
    int dst = ei[N_EDGES + eid];

    float4 ev = __ldg(reinterpret_cast<const float4*>(efeat) + eid);

    const uint4* tp = reinterpret_cast<const uint4*>(g_t + (unsigned)src * 64u + j * 16u);
    uint4 ta = __ldg(tp);
    uint4 tb = __ldg(tp + 1);
    uint2 tbr = __ldg(reinterpret_cast<const uint2*>(g_tb + (unsigned)src * 16u + j * 4u));

#define H2F(u) __half22float2(*reinterpret_cast<__half2*>(&(u)))
    float2 b01 = H2F(tbr.x), b23 = H2F(tbr.y);
    float2 c0 = H2F(ta.x), c1 = H2F(ta.y), c2 = H2F(ta.z), c3 = H2F(ta.w);
    float2 c4 = H2F(tb.x), c5 = H2F(tb.y), c6 = H2F(tb.z), c7 = H2F(tb.w);
#undef H2F
    float m0 = fmaf(ev.x, c0.x, fmaf(ev.y, c0.y, fmaf(ev.z, c1.x, fmaf(ev.w, c1.y, b01.x))));
    float m1 = fmaf(ev.x, c2.x, fmaf(ev.y, c2.y, fmaf(ev.z, c3.x, fmaf(ev.w, c3.y, b01.y))));
    float m2 = fmaf(ev.x, c4.x, fmaf(ev.y, c4.y, fmaf(ev.z, c5.x, fmaf(ev.w, c5.y, b23.x))));
    float m3 = fmaf(ev.x, c6.x, fmaf(ev.y, c6.y, fmaf(ev.z, c7.x, fmaf(ev.w, c7.y, b23.y))));

    float* outp = g_sum + (unsigned)dst * 16u + j * 4u;
    asm volatile("red.global.add.v4.f32 [%0], {%1, %2, %3, %4};"
                 :: "l"(outp), "f"(m0), "f"(m1), "f"(m2), "f"(m3) : "memory");
    if (j == 0) {
        float* cp = g_cnt + dst;
        asm volatile("red.global.add.f32 [%0], %1;" :: "l"(cp), "f"(1.0f) : "memory");
    }
}

// ---------------------------------------------------------------------------
// K3 (launch 3): fused finalize + BatchNorm + LeakyReLU with software
// grid barrier (592 blocks <= full residency; cannot deadlock).
// ---------------------------------------------------------------------------
__global__ void __launch_bounds__(256) k_finalbn(
    float* __restrict__ out,
    const float* __restrict__ gamma,
    const float* __restrict__ beta)
{
    int t = threadIdx.x;
    int idx = blockIdx.x * 256 + t;
    const float4* s4 = reinterpret_cast<const float4*>(g_sum);
    const float4* r4 = reinterpret_cast<const float4*>(g_r);
    float4* o4 = reinterpret_cast<float4*>(out);

    float4 vals[3];
    float s1x = 0.f, s1y = 0.f, s1z = 0.f, s1w = 0.f;
    float s2x = 0.f, s2y = 0.f, s2z = 0.f, s2w = 0.f;
#pragma unroll
    for (int k = 0; k < 3; k++) {
        int i = idx + k * FB_STRIDE;
        if (i < N4) {
            int n = i >> 2;
            float inv = 1.0f / fmaxf(g_cnt[n], 1.0f);
            float4 s = s4[i];
            float4 r = r4[i];
            float4 val;
            val.x = fmaf(s.x, inv, r.x);
            val.y = fmaf(s.y, inv, r.y);
            val.z = fmaf(s.z, inv, r.z);
            val.w = fmaf(s.w, inv, r.w);
            vals[k] = val;
            s1x += val.x; s1y += val.y; s1z += val.z; s1w += val.w;
            s2x = fmaf(val.x, val.x, s2x);
            s2y = fmaf(val.y, val.y, s2y);
            s2z = fmaf(val.z, val.z, s2z);
            s2w = fmaf(val.w, val.w, s2w);
        }
    }

#pragma unroll
    for (int m = 4; m <= 16; m <<= 1) {
        s1x += __shfl_xor_sync(0xffffffffu, s1x, m);
        s1y += __shfl_xor_sync(0xffffffffu, s1y, m);
        s1z += __shfl_xor_sync(0xffffffffu, s1z, m);
        s1w += __shfl_xor_sync(0xffffffffu, s1w, m);
        s2x += __shfl_xor_sync(0xffffffffu, s2x, m);
        s2y += __shfl_xor_sync(0xffffffffu, s2y, m);
        s2z += __shfl_xor_sync(0xffffffffu, s2z, m);
        s2w += __shfl_xor_sync(0xffffffffu, s2w, m);
    }
    __shared__ float sm1[8][4][4];
    __shared__ float sm2[8][4][4];
    int warp = t >> 5;
    int lane = t & 31;
    if (lane < 4) {
        sm1[warp][lane][0] = s1x; sm1[warp][lane][1] = s1y;
        sm1[warp][lane][2] = s1z; sm1[warp][lane][3] = s1w;
        sm2[warp][lane][0] = s2x; sm2[warp][lane][1] = s2y;
        sm2[warp][lane][2] = s2z; sm2[warp][lane][3] = s2w;
    }
    __syncthreads();
    if (t < 16) {
        float a1 = 0.f, a2 = 0.f;
#pragma unroll
        for (int w = 0; w < 8; w++) {
            a1 += sm1[w][t >> 2][t & 3];
            a2 += sm2[w][t >> 2][t & 3];
        }
        atomicAdd(&g_s1[t], a1);
        atomicAdd(&g_s2[t], a2);
    }

    __threadfence();
    __syncthreads();
    if (t == 0) {
        atomicAdd(&g_ctr, 1);
        while (atomicAdd(&g_ctr, 0) < FB_GRID) { }
    }
    __syncthreads();

    int ob = (idx & 3) * 4;
    const float invN = 1.0f / (float)N_NODES;
    float scale[4], shift[4];
#pragma unroll
    for (int k = 0; k < 4; k++) {
        int o = ob + k;
        float mu = __ldcg(&g_s1[o]) * invN;
        float var = __ldcg(&g_s2[o]) * invN - mu * mu;
        float sc = gamma[o] * rsqrtf(var + 1e-5f);
        scale[k] = sc;
        shift[k] = beta[o] - sc * mu;
    }
#pragma unroll
    for (int k = 0; k < 3; k++) {
        int i = idx + k * FB_STRIDE;
        if (i < N4) {
            float4 val = vals[k];
            float x0 = fmaf(val.x, scale[0], shift[0]);
            float x1 = fmaf(val.y, scale[1], shift[1]);
            float x2 = fmaf(val.z, scale[2], shift[2]);
            float x3 = fmaf(val.w, scale[3], shift[3]);
            float4 res;
            res.x = (x0 >= 0.0f) ? x0 : 0.01f * x0;
            res.y = (x1 >= 0.0f) ? x1 : 0.01f * x1;
            res.z = (x2 >= 0.0f) ? x2 : 0.01f * x2;
            res.w = (x3 >= 0.0f) ? x3 : 0.01f * x3;
            o4[i] = res;
        }
    }
}

// ---------------------------------------------------------------------------
extern "C" void kernel_launch(void* const* d_in, const int* in_sizes, int n_in,
                              void* d_out, int out_size) {
    const float* v      = (const float*)d_in[0];
    const float* e      = (const float*)d_in[1];
    const int*   ei     = (const int*)  d_in[2];
    const float* enet_w = (const float*)d_in[3];
    const float* enet_b = (const float*)d_in[4];
    const float* root   = (const float*)d_in[5];
    const float* bias   = (const float*)d_in[6];
    const float* gamma  = (const float*)d_in[7];
    const float* beta   = (const float*)d_in[8];
    float* out = (float*)d_out;

    k_node_pre<<<N_NODES / 16, 256>>>(v, enet_w, enet_b, root, bias);  // launch 1
    k_edge    <<<(N_EDGES * 4) / 256, 256>>>(e, ei);                   // launch 2
    k_finalbn <<<FB_GRID, 256>>>(out, gamma, beta);                    // launch 3
}

// round 11
// speedup vs baseline: 1.1947x; 1.1596x over previous
#include <cuda_runtime.h>
#include <cuda_fp16.h>

#define N_NODES 100000
#define N_EDGES 1000000
#define FB_GRID 592
#define FB_STRIDE (FB_GRID * 256)          // 151552
#define N4 (N_NODES * 4)                   // 400000 float4 slots
#define NP_GRID 444                        // 148 SMs x 3 CTAs
#define NP_WARPS (NP_GRID * 8)             // 3552 warps

typedef unsigned long long ull;

#define PACK2(d, lo, hi)  asm("mov.b64 %0, {%1, %2};" : "=l"(d) : "f"(lo), "f"(hi))
#define UNPACK2(lo, hi, s) asm("mov.b64 {%0, %1}, %2;" : "=f"(lo), "=f"(hi) : "l"(s))
#define FMA2(d, a, b, c)  asm("fma.rn.f32x2 %0, %1, %2, %3;" : "=l"(d) : "l"(a), "l"(b), "l"(c))

__device__ __half g_t[N_NODES * 64];    // [n][o][c] fp16: t[n,o,c] = sum_i v[n,i]*W[i*16+o][c]
__device__ __half g_tb[N_NODES * 16];   // [n][o]    fp16: tb[n,o] = sum_i v[n,i]*b[i*16+o]
__device__ float  g_r[N_NODES * 16];    // [n][o]    fp32: v@root + bias (node-local term)
__device__ float  g_sum[N_NODES * 16];  // scatter accumulator
__device__ float  g_cnt[N_NODES];       // degree accumulator
__device__ float  g_s1[16];             // batch sum per feature
__device__ float  g_s2[16];             // batch sum-of-squares per feature
__device__ int    g_ctr;                // grid-barrier counter

// ---------------------------------------------------------------------------
// K1 (launch 1): per-node precompute of t/tb/r + fused zeroing.
// One warp per node. Lane = (cp, o): cp = lane>>4, o = lane&15.
// Weights live in registers (loaded once, amortized over ~28 nodes/warp).
// No shared memory in the hot loop.
// ---------------------------------------------------------------------------
__global__ void __launch_bounds__(256) k_node_pre(
    const float* __restrict__ v,
    const float* __restrict__ enet_w,   // [256][4]
    const float* __restrict__ enet_b,   // [256]
    const float* __restrict__ root,     // [16][16] (i,o)
    const float* __restrict__ bias)     // [16]
{
    int t = threadIdx.x;
    int lane = t & 31;
    int warp = t >> 5;
    int cp = lane >> 4;        // which c-pair (0: c0,c1 / 1: c2,c3)
    int o = lane & 15;

    // --- fused zeroing (grid-stride) ---
    unsigned gid = blockIdx.x * 256u + t;
    unsigned gstride = NP_GRID * 256u;
    const float4 z4 = make_float4(0.f, 0.f, 0.f, 0.f);
    for (unsigned i = gid; i < N4; i += gstride)
        reinterpret_cast<float4*>(g_sum)[i] = z4;
    for (unsigned i = gid; i < N_NODES; i += gstride) g_cnt[i] = 0.0f;
    if (gid < 16) { g_s1[gid] = 0.0f; g_s2[gid] = 0.0f; }
    if (gid == 16) g_ctr = 0;

    // --- register-resident weights ---
    ull w2[16];        // (W[i*16+o][2cp], W[i*16+o][2cp+1])
    float br[16];      // cp==0: enet_b[i*16+o] ; cp==1: root[i*16+o]
    const float* brbase = (cp == 0) ? enet_b : root;
#pragma unroll
    for (int i = 0; i < 16; i++) {
        int j = i * 16 + o;
        float2 wp = __ldg(reinterpret_cast<const float2*>(enet_w + j * 4 + cp * 2));
        PACK2(w2[i], wp.x, wp.y);
        br[i] = __ldg(brbase + j);
    }
    float b0 = (cp == 0) ? 0.0f : bias[o];   // r accumulates bias; tb starts at 0

    // --- node loop: one warp per node ---
    int wg = blockIdx.x * 8 + warp;
    for (int n = wg; n < N_NODES; n += NP_WARPS) {
        const float4* vp = reinterpret_cast<const float4*>(v + (unsigned)n * 16u);
        float4 x0 = __ldg(vp);
        float4 x1 = __ldg(vp + 1);
        float4 x2 = __ldg(vp + 2);
        float4 x3 = __ldg(vp + 3);
        float vv[16] = {x0.x, x0.y, x0.z, x0.w, x1.x, x1.y, x1.z, x1.w,
                        x2.x, x2.y, x2.z, x2.w, x3.x, x3.y, x3.z, x3.w};

        ull a;
        PACK2(a, 0.0f, 0.0f);
        float ab = b0;
#pragma unroll
        for (int i = 0; i < 16; i++) {
            ull vb;
            PACK2(vb, vv[i], vv[i]);
            FMA2(a, vb, w2[i], a);
            ab = fmaf(vv[i], br[i], ab);
        }
        float a0, a1;
        UNPACK2(a0, a1, a);
        __half2 h = __floats2half2_rn(a0, a1);
        // t[n, o, 2cp..2cp+1] at halves offset n*64 + o*4 + cp*2
        *reinterpret_cast<__half2*>(g_t + (unsigned)n * 64u + o * 4u + cp * 2u) = h;
        if (cp == 0) g_tb[(unsigned)n * 16u + o] = __float2half_rn(ab);
        else         g_r[(unsigned)n * 16u + o] = ab;
    }
}

// ---------------------------------------------------------------------------
// K2 (launch 2): per-edge message + vector RED scatter. (unchanged)
// ---------------------------------------------------------------------------
__global__ void __launch_bounds__(256) k_edge(
    const float* __restrict__ efeat,
    const int* __restrict__ ei)   // [2][E] row0=src, row1=dst
{
    unsigned gid = blockIdx.x * 256u + threadIdx.x;
    unsigned eid = gid >> 2;
    unsigned j = gid & 3u;
    if (eid >= N_EDGES) return;

    int src = ei[eid];
    int dst = ei[N_EDGES + eid];

    float4 ev = __ldg(reinterpret_cast<const float4*>(efeat) + eid);

    const uint4* tp = reinterpret_cast<const uint4*>(g_t + (unsigned)src * 64u + j * 16u);
    uint4 ta = __ldg(tp);
    uint4 tb = __ldg(tp + 1);
    uint2 tbr = __ldg(reinterpret_cast<const uint2*>(g_tb + (unsigned)src * 16u + j * 4u));

#define H2F(u) __half22float2(*reinterpret_cast<__half2*>(&(u)))
    float2 b01 = H2F(tbr.x), b23 = H2F(tbr.y);
    float2 c0 = H2F(ta.x), c1 = H2F(ta.y), c2 = H2F(ta.z), c3 = H2F(ta.w);
    float2 c4 = H2F(tb.x), c5 = H2F(tb.y), c6 = H2F(tb.z), c7 = H2F(tb.w);
#undef H2F
    float m0 = fmaf(ev.x, c0.x, fmaf(ev.y, c0.y, fmaf(ev.z, c1.x, fmaf(ev.w, c1.y, b01.x))));
    float m1 = fmaf(ev.x, c2.x, fmaf(ev.y, c2.y, fmaf(ev.z, c3.x, fmaf(ev.w, c3.y, b01.y))));
    float m2 = fmaf(ev.x, c4.x, fmaf(ev.y, c4.y, fmaf(ev.z, c5.x, fmaf(ev.w, c5.y, b23.x))));
    float m3 = fmaf(ev.x, c6.x, fmaf(ev.y, c6.y, fmaf(ev.z, c7.x, fmaf(ev.w, c7.y, b23.y))));

    float* outp = g_sum + (unsigned)dst * 16u + j * 4u;
    asm volatile("red.global.add.v4.f32 [%0], {%1, %2, %3, %4};"
                 :: "l"(outp), "f"(m0), "f"(m1), "f"(m2), "f"(m3) : "memory");
    if (j == 0) {
        float* cp = g_cnt + dst;
        asm volatile("red.global.add.f32 [%0], %1;" :: "l"(cp), "f"(1.0f) : "memory");
    }
}

// ---------------------------------------------------------------------------
// K3 (launch 3): fused finalize + BatchNorm + LeakyReLU with software
// grid barrier (592 blocks <= full residency; cannot deadlock). (unchanged)
// ---------------------------------------------------------------------------
__global__ void __launch_bounds__(256) k_finalbn(
    float* __restrict__ out,
    const float* __restrict__ gamma,
    const float* __restrict__ beta)
{
    int t = threadIdx.x;
    int idx = blockIdx.x * 256 + t;
    const float4* s4 = reinterpret_cast<const float4*>(g_sum);
    const float4* r4 = reinterpret_cast<const float4*>(g_r);
    float4* o4 = reinterpret_cast<float4*>(out);

    float4 vals[3];
    float s1x = 0.f, s1y = 0.f, s1z = 0.f, s1w = 0.f;
    float s2x = 0.f, s2y = 0.f, s2z = 0.f, s2w = 0.f;
#pragma unroll
    for (int k = 0; k < 3; k++) {
        int i = idx + k * FB_STRIDE;
        if (i < N4) {
            int n = i >> 2;
            float inv = 1.0f / fmaxf(g_cnt[n], 1.0f);
            float4 s = s4[i];
            float4 r = r4[i];
            float4 val;
            val.x = fmaf(s.x, inv, r.x);
            val.y = fmaf(s.y, inv, r.y);
            val.z = fmaf(s.z, inv, r.z);
            val.w = fmaf(s.w, inv, r.w);
            vals[k] = val;
            s1x += val.x; s1y += val.y; s1z += val.z; s1w += val.w;
            s2x = fmaf(val.x, val.x, s2x);
            s2y = fmaf(val.y, val.y, s2y);
            s2z = fmaf(val.z, val.z, s2z);
            s2w = fmaf(val.w, val.w, s2w);
        }
    }

#pragma unroll
    for (int m = 4; m <= 16; m <<= 1) {
        s1x += __shfl_xor_sync(0xffffffffu, s1x, m);
        s1y += __shfl_xor_sync(0xffffffffu, s1y, m);
        s1z += __shfl_xor_sync(0xffffffffu, s1z, m);
        s1w += __shfl_xor_sync(0xffffffffu, s1w, m);
        s2x += __shfl_xor_sync(0xffffffffu, s2x, m);
        s2y += __shfl_xor_sync(0xffffffffu, s2y, m);
        s2z += __shfl_xor_sync(0xffffffffu, s2z, m);
        s2w += __shfl_xor_sync(0xffffffffu, s2w, m);
    }
    __shared__ float sm1[8][4][4];
    __shared__ float sm2[8][4][4];
    int warp = t >> 5;
    int lane = t & 31;
    if (lane < 4) {
        sm1[warp][lane][0] = s1x; sm1[warp][lane][1] = s1y;
        sm1[warp][lane][2] = s1z; sm1[warp][lane][3] = s1w;
        sm2[warp][lane][0] = s2x; sm2[warp][lane][1] = s2y;
        sm2[warp][lane][2] = s2z; sm2[warp][lane][3] = s2w;
    }
    __syncthreads();
    if (t < 16) {
        float a1 = 0.f, a2 = 0.f;
#pragma unroll
        for (int w = 0; w < 8; w++) {
            a1 += sm1[w][t >> 2][t & 3];
            a2 += sm2[w][t >> 2][t & 3];
        }
        atomicAdd(&g_s1[t], a1);
        atomicAdd(&g_s2[t], a2);
    }

    __threadfence();
    __syncthreads();
    if (t == 0) {
        atomicAdd(&g_ctr, 1);
        while (atomicAdd(&g_ctr, 0) < FB_GRID) { }
    }
    __syncthreads();

    int ob = (idx & 3) * 4;
    const float invN = 1.0f / (float)N_NODES;
    float scale[4], shift[4];
#pragma unroll
    for (int k = 0; k < 4; k++) {
        int o = ob + k;
        float mu = __ldcg(&g_s1[o]) * invN;
        float var = __ldcg(&g_s2[o]) * invN - mu * mu;
        float sc = gamma[o] * rsqrtf(var + 1e-5f);
        scale[k] = sc;
        shift[k] = beta[o] - sc * mu;
    }
#pragma unroll
    for (int k = 0; k < 3; k++) {
        int i = idx + k * FB_STRIDE;
        if (i < N4) {
            float4 val = vals[k];
            float x0 = fmaf(val.x, scale[0], shift[0]);
            float x1 = fmaf(val.y, scale[1], shift[1]);
            float x2 = fmaf(val.z, scale[2], shift[2]);
            float x3 = fmaf(val.w, scale[3], shift[3]);
            float4 res;
            res.x = (x0 >= 0.0f) ? x0 : 0.01f * x0;
            res.y = (x1 >= 0.0f) ? x1 : 0.01f * x1;
            res.z = (x2 >= 0.0f) ? x2 : 0.01f * x2;
            res.w = (x3 >= 0.0f) ? x3 : 0.01f * x3;
            o4[i] = res;
        }
    }
}

// ---------------------------------------------------------------------------
extern "C" void kernel_launch(void* const* d_in, const int* in_sizes, int n_in,
                              void* d_out, int out_size) {
    const float* v      = (const float*)d_in[0];
    const float* e      = (const float*)d_in[1];
    const int*   ei     = (const int*)  d_in[2];
    const float* enet_w = (const float*)d_in[3];
    const float* enet_b = (const float*)d_in[4];
    const float* root   = (const float*)d_in[5];
    const float* bias   = (const float*)d_in[6];
    const float* gamma  = (const float*)d_in[7];
    const float* beta   = (const float*)d_in[8];
    float* out = (float*)d_out;

    k_node_pre<<<NP_GRID, 256>>>(v, enet_w, enet_b, root, bias);  // launch 1
    k_edge    <<<(N_EDGES * 4) / 256, 256>>>(e, ei);              // launch 2
    k_finalbn <<<FB_GRID, 256>>>(out, gamma, beta);               // launch 3
}

// round 12
// speedup vs baseline: 1.1999x; 1.0043x over previous
#include <cuda_runtime.h>
#include <cuda_fp16.h>

#define N_NODES 100000
#define N_EDGES 1000000
#define FB_GRID 592
#define FB_STRIDE (FB_GRID * 256)          // 151552
#define N4 (N_NODES * 4)                   // 400000 float4 slots
#define NP_GRID 444                        // 148 SMs x 3 CTAs
#define NP_WARPS (NP_GRID * 8)             // 3552 warps

__device__ __half g_t[N_NODES * 64];    // [n][o][c] fp16: t[n,o,c] = sum_i v[n,i]*W[i*16+o][c]
__device__ __half g_tb[N_NODES * 16];   // [n][o]    fp16: tb[n,o] = sum_i v[n,i]*b[i*16+o]
__device__ float  g_r[N_NODES * 16];    // [n][o]    fp32: v@root + bias (node-local term)
__device__ float  g_sum[N_NODES * 16];  // scatter accumulator
__device__ float  g_cnt[N_NODES];       // degree accumulator
__device__ float  g_s1[16];             // batch sum per feature
__device__ float  g_s2[16];             // batch sum-of-squares per feature
__device__ int    g_ctr;                // grid-barrier counter

// ---------------------------------------------------------------------------
// K1 (launch 1): per-node precompute of t/tb/r + fused zeroing.
// One warp per node-pair; lane = (cp, o): cp = lane>>4, o = lane&15.
// Weights register-resident; plain scalar FFMA; 2 nodes in flight per warp
// (8 independent LDG.128 + 6 independent FMA chains) to hide L2 latency.
// ---------------------------------------------------------------------------
__global__ void __launch_bounds__(256) k_node_pre(
    const float* __restrict__ v,
    const float* __restrict__ enet_w,   // [256][4]
    const float* __restrict__ enet_b,   // [256]
    const float* __restrict__ root,     // [16][16] (i,o)
    const float* __restrict__ bias)     // [16]
{
    int t = threadIdx.x;
    int lane = t & 31;
    int warp = t >> 5;
    int cp = lane >> 4;        // which c-pair (0: c0,c1 / 1: c2,c3)
    int o = lane & 15;

    // --- fused zeroing (grid-stride) ---
    unsigned gid = blockIdx.x * 256u + t;
    unsigned gstride = NP_GRID * 256u;
    const float4 z4 = make_float4(0.f, 0.f, 0.f, 0.f);
    for (unsigned i = gid; i < N4; i += gstride)
        reinterpret_cast<float4*>(g_sum)[i] = z4;
    for (unsigned i = gid; i < N_NODES; i += gstride) g_cnt[i] = 0.0f;
    if (gid < 16) { g_s1[gid] = 0.0f; g_s2[gid] = 0.0f; }
    if (gid == 16) g_ctr = 0;

    // --- register-resident weights ---
    float w0[16], w1[16], br[16];
    const float* brbase = (cp == 0) ? enet_b : root;
#pragma unroll
    for (int i = 0; i < 16; i++) {
        int j = i * 16 + o;
        float2 wp = __ldg(reinterpret_cast<const float2*>(enet_w + j * 4 + cp * 2));
        w0[i] = wp.x;
        w1[i] = wp.y;
        br[i] = __ldg(brbase + j);
    }
    float b0 = (cp == 0) ? 0.0f : bias[o];   // r accumulates bias; tb starts at 0

    // --- node loop: 2 nodes in flight per warp ---
    int wg = blockIdx.x * 8 + warp;
    for (int n0 = wg; n0 < N_NODES; n0 += 2 * NP_WARPS) {
        int n1 = n0 + NP_WARPS;
        bool has1 = (n1 < N_NODES);
        int n1c = has1 ? n1 : n0;

        const float4* vp0 = reinterpret_cast<const float4*>(v + (unsigned)n0 * 16u);
        const float4* vp1 = reinterpret_cast<const float4*>(v + (unsigned)n1c * 16u);
        float4 A0 = __ldg(vp0), A1 = __ldg(vp0 + 1), A2 = __ldg(vp0 + 2), A3 = __ldg(vp0 + 3);
        float4 B0 = __ldg(vp1), B1 = __ldg(vp1 + 1), B2 = __ldg(vp1 + 2), B3 = __ldg(vp1 + 3);

        float va[16] = {A0.x, A0.y, A0.z, A0.w, A1.x, A1.y, A1.z, A1.w,
                        A2.x, A2.y, A2.z, A2.w, A3.x, A3.y, A3.z, A3.w};
        float vb[16] = {B0.x, B0.y, B0.z, B0.w, B1.x, B1.y, B1.z, B1.w,
                        B2.x, B2.y, B2.z, B2.w, B3.x, B3.y, B3.z, B3.w};

        float x0 = 0.f, x1 = 0.f, xb = b0;
        float y0 = 0.f, y1 = 0.f, yb = b0;
#pragma unroll
        for (int i = 0; i < 16; i++) {
            x0 = fmaf(va[i], w0[i], x0);
            y0 = fmaf(vb[i], w0[i], y0);
            x1 = fmaf(va[i], w1[i], x1);
            y1 = fmaf(vb[i], w1[i], y1);
            xb = fmaf(va[i], br[i], xb);
            yb = fmaf(vb[i], br[i], yb);
        }

        {
            __half2 h = __floats2half2_rn(x0, x1);
            *reinterpret_cast<__half2*>(g_t + (unsigned)n0 * 64u + o * 4u + cp * 2u) = h;
            if (cp == 0) g_tb[(unsigned)n0 * 16u + o] = __float2half_rn(xb);
            else         g_r[(unsigned)n0 * 16u + o] = xb;
        }
        if (has1) {
            __half2 h = __floats2half2_rn(y0, y1);
            *reinterpret_cast<__half2*>(g_t + (unsigned)n1 * 64u + o * 4u + cp * 2u) = h;
            if (cp == 0) g_tb[(unsigned)n1 * 16u + o] = __float2half_rn(yb);
            else         g_r[(unsigned)n1 * 16u + o] = yb;
        }
    }
}

// ---------------------------------------------------------------------------
// K2 (launch 2): per-edge message + vector RED scatter. (unchanged)
// ---------------------------------------------------------------------------
__global__ void __launch_bounds__(256) k_edge(
    const float* __restrict__ efeat,
    const int* __restrict__ ei)   // [2][E] row0=src, row1=dst
{
    unsigned gid = blockIdx.x * 256u + threadIdx.x;
    unsigned eid = gid >> 2;
    unsigned j = gid & 3u;
    if (eid >= N_EDGES) return;

    int src = ei[eid];
    int dst = ei[N_EDGES + eid];

    float4 ev = __ldg(reinterpret_cast<const float4*>(efeat) + eid);

    const uint4* tp = reinterpret_cast<const uint4*>(g_t + (unsigned)src * 64u + j * 16u);
    uint4 ta = __ldg(tp);
    uint4 tb = __ldg(tp + 1);
    uint2 tbr = __ldg(reinterpret_cast<const uint2*>(g_tb + (unsigned)src * 16u + j * 4u));

#define H2F(u) __half22float2(*reinterpret_cast<__half2*>(&(u)))
    float2 b01 = H2F(tbr.x), b23 = H2F(tbr.y);
    float2 c0 = H2F(ta.x), c1 = H2F(ta.y), c2 = H2F(ta.z), c3 = H2F(ta.w);
    float2 c4 = H2F(tb.x), c5 = H2F(tb.y), c6 = H2F(tb.z), c7 = H2F(tb.w);
#undef H2F
    float m0 = fmaf(ev.x, c0.x, fmaf(ev.y, c0.y, fmaf(ev.z, c1.x, fmaf(ev.w, c1.y, b01.x))));
    float m1 = fmaf(ev.x, c2.x, fmaf(ev.y, c2.y, fmaf(ev.z, c3.x, fmaf(ev.w, c3.y, b01.y))));
    float m2 = fmaf(ev.x, c4.x, fmaf(ev.y, c4.y, fmaf(ev.z, c5.x, fmaf(ev.w, c5.y, b23.x))));
    float m3 = fmaf(ev.x, c6.x, fmaf(ev.y, c6.y, fmaf(ev.z, c7.x, fmaf(ev.w, c7.y, b23.y))));

    float* outp = g_sum + (unsigned)dst * 16u + j * 4u;
    asm volatile("red.global.add.v4.f32 [%0], {%1, %2, %3, %4};"
                 :: "l"(outp), "f"(m0), "f"(m1), "f"(m2), "f"(m3) : "memory");
    if (j == 0) {
        float* cp = g_cnt + dst;
        asm volatile("red.global.add.f32 [%0], %1;" :: "l"(cp), "f"(1.0f) : "memory");
    }
}

// ---------------------------------------------------------------------------
// K3 (launch 3): fused finalize + BatchNorm + LeakyReLU with software
// grid barrier (592 blocks <= full residency; cannot deadlock). (unchanged)
// ---------------------------------------------------------------------------
__global__ void __launch_bounds__(256) k_finalbn(
    float* __restrict__ out,
    const float* __restrict__ gamma,
    const float* __restrict__ beta)
{
    int t = threadIdx.x;
    int idx = blockIdx.x * 256 + t;
    const float4* s4 = reinterpret_cast<const float4*>(g_sum);
    const float4* r4 = reinterpret_cast<const float4*>(g_r);
    float4* o4 = reinterpret_cast<float4*>(out);

    float4 vals[3];
    float s1x = 0.f, s1y = 0.f, s1z = 0.f, s1w = 0.f;
    float s2x = 0.f, s2y = 0.f, s2z = 0.f, s2w = 0.f;
#pragma unroll
    for (int k = 0; k < 3; k++) {
        int i = idx + k * FB_STRIDE;
        if (i < N4) {
            int n = i >> 2;
            float inv = 1.0f / fmaxf(g_cnt[n], 1.0f);
            float4 s = s4[i];
            float4 r = r4[i];
            float4 val;
            val.x = fmaf(s.x, inv, r.x);
            val.y = fmaf(s.y, inv, r.y);
            val.z = fmaf(s.z, inv, r.z);
            val.w = fmaf(s.w, inv, r.w);
            vals[k] = val;
            s1x += val.x; s1y += val.y; s1z += val.z; s1w += val.w;
            s2x = fmaf(val.x, val.x, s2x);
            s2y = fmaf(val.y, val.y, s2y);
            s2z = fmaf(val.z, val.z, s2z);
            s2w = fmaf(val.w, val.w, s2w);
        }
    }

#pragma unroll
    for (int m = 4; m <= 16; m <<= 1) {
        s1x += __shfl_xor_sync(0xffffffffu, s1x, m);
        s1y += __shfl_xor_sync(0xffffffffu, s1y, m);
        s1z += __shfl_xor_sync(0xffffffffu, s1z, m);
        s1w += __shfl_xor_sync(0xffffffffu, s1w, m);
        s2x += __shfl_xor_sync(0xffffffffu, s2x, m);
        s2y += __shfl_xor_sync(0xffffffffu, s2y, m);
        s2z += __shfl_xor_sync(0xffffffffu, s2z, m);
        s2w += __shfl_xor_sync(0xffffffffu, s2w, m);
    }
    __shared__ float sm1[8][4][4];
    __shared__ float sm2[8][4][4];
    int warp = t >> 5;
    int lane = t & 31;
    if (lane < 4) {
        sm1[warp][lane][0] = s1x; sm1[warp][lane][1] = s1y;
        sm1[warp][lane][2] = s1z; sm1[warp][lane][3] = s1w;
        sm2[warp][lane][0] = s2x; sm2[warp][lane][1] = s2y;
        sm2[warp][lane][2] = s2z; sm2[warp][lane][3] = s2w;
    }
    __syncthreads();
    if (t < 16) {
        float a1 = 0.f, a2 = 0.f;
#pragma unroll
        for (int w = 0; w < 8; w++) {
            a1 += sm1[w][t >> 2][t & 3];
            a2 += sm2[w][t >> 2][t & 3];
        }
        atomicAdd(&g_s1[t], a1);
        atomicAdd(&g_s2[t], a2);
    }

    __threadfence();
    __syncthreads();
    if (t == 0) {
        atomicAdd(&g_ctr, 1);
        while (atomicAdd(&g_ctr, 0) < FB_GRID) { }
    }
    __syncthreads();

    int ob = (idx & 3) * 4;
    const float invN = 1.0f / (float)N_NODES;
    float scale[4], shift[4];
#pragma unroll
    for (int k = 0; k < 4; k++) {
        int o = ob + k;
        float mu = __ldcg(&g_s1[o]) * invN;
        float var = __ldcg(&g_s2[o]) * invN - mu * mu;
        float sc = gamma[o] * rsqrtf(var + 1e-5f);
        scale[k] = sc;
        shift[k] = beta[o] - sc * mu;
    }
#pragma unroll
    for (int k = 0; k < 3; k++) {
        int i = idx + k * FB_STRIDE;
        if (i < N4) {
            float4 val = vals[k];
            float x0 = fmaf(val.x, scale[0], shift[0]);
            float x1 = fmaf(val.y, scale[1], shift[1]);
            float x2 = fmaf(val.z, scale[2], shift[2]);
            float x3 = fmaf(val.w, scale[3], shift[3]);
            float4 res;
            res.x = (x0 >= 0.0f) ? x0 : 0.01f * x0;
            res.y = (x1 >= 0.0f) ? x1 : 0.01f * x1;
            res.z = (x2 >= 0.0f) ? x2 : 0.01f * x2;
            res.w = (x3 >= 0.0f) ? x3 : 0.01f * x3;
            o4[i] = res;
        }
    }
}

// ---------------------------------------------------------------------------
extern "C" void kernel_launch(void* const* d_in, const int* in_sizes, int n_in,
                              void* d_out, int out_size) {
    const float* v      = (const float*)d_in[0];
    const float* e      = (const float*)d_in[1];
    const int*   ei     = (const int*)  d_in[2];
    const float* enet_w = (const float*)d_in[3];
    const float* enet_b = (const float*)d_in[4];
    const float* root   = (const float*)d_in[5];
    const float* bias   = (const float*)d_in[6];
    const float* gamma  = (const float*)d_in[7];
    const float* beta   = (const float*)d_in[8];
    float* out = (float*)d_out;

    k_node_pre<<<NP_GRID, 256>>>(v, enet_w, enet_b, root, bias);  // launch 1
    k_edge    <<<(N_EDGES * 4) / 256, 256>>>(e, ei);              // launch 2
    k_finalbn <<<FB_GRID, 256>>>(out, gamma, beta);               // launch 3
}